// round 5
// baseline (speedup 1.0000x reference)
#include <cuda_runtime.h>
#include <cstddef>

#define Bn 8
#define Cn 4
#define Hn 768
#define Wn 768
#define Rr 8
#define NCH 19
#define EPSc 1e-4f

// A-sum and b intermediate (only 2 channels survive stage 1)
__device__ float g_Ab[(size_t)2 * Bn * Hn * Wn];

// channel -> (planeA, planeB); plane 4 = p, 0..3 = I_c, B=-1 -> identity
__constant__ int c_chA[NCH] = {0,1,2,3, 4, 4,4,4,4, 0,0,0,0,1,1,1,2,2,3};
__constant__ int c_chB[NCH] = {-1,-1,-1,-1, -1, 0,1,2,3, 0,1,2,3,1,2,3,2,3,3};

__device__ __forceinline__ int wcnt(int t, int L) {
    int lo = t - Rr; if (lo < 0) lo = 0;
    int hi = t + Rr; if (hi > L - 1) hi = L - 1;
    return hi - lo + 1;
}

// ---------------------------------------------------------------------------
// Stage 1: fused products + 2D box (tile-local) + per-pixel 4x4 SPD solve.
// Tile 32x32, halo 8 -> extended 48x48. 1024 threads (1 CTA/SM, 32 warps).
// SMEM layout (floats):
//   hs  [0, 30096)              : 19 ch x 48 rows x 33 (pad)
//   raw [30096, 41856)          : 5 planes x 48 rows x 49 (pad)   (phase 0-1)
//   out [30096, 49552)          : 19 ch x 32 x 32                 (phase 2-3, aliases raw)
// ---------------------------------------------------------------------------
#define T1 32
#define E1 48
#define RP1 49
#define HP1 33
#define NT1 1024
#define SZ_HS (NCH * E1 * HP1)     // 30096
#define SZ_OUT (NCH * T1 * T1)     // 19456
#define SMEM1_BYTES ((SZ_HS + SZ_OUT) * 4)   // 198208

__global__ __launch_bounds__(NT1) void k_stage1(const float* __restrict__ I,
                                                const float* __restrict__ p) {
    extern __shared__ float sm[];
    float* hs  = sm;
    float* raw = sm + SZ_HS;
    float* out = sm + SZ_HS;   // aliases raw (raw dead after phase 1)

    int b  = blockIdx.z;
    int X0 = blockIdx.x * T1, Y0 = blockIdx.y * T1;
    int tid = threadIdx.x;

    // ---- Phase 0: load raw halo tile (5 planes, zero-padded) ----
    for (int i = tid; i < 5 * E1 * E1; i += NT1) {
        int pl = i / (E1 * E1);
        int r  = i % (E1 * E1);
        int ey = r / E1, ex = r % E1;
        int gy = Y0 - Rr + ey, gx = X0 - Rr + ex;
        float v = 0.f;
        if (gx >= 0 && gx < Wn && gy >= 0 && gy < Hn)
            v = (pl < 4) ? I[(((size_t)b * Cn + pl) * Hn + gy) * Wn + gx]
                         : p[((size_t)b * Hn + gy) * Wn + gx];
        raw[(pl * E1 + ey) * RP1 + ex] = v;
    }
    __syncthreads();

    // ---- Phase 1: horizontal 17-tap box of 19 product channels (912 tasks) ----
    for (int t = tid; t < NCH * E1; t += NT1) {
        int ey = t % E1, ch = t / E1;
        const float* ra = raw + (c_chA[ch] * E1 + ey) * RP1;
        int bb = c_chB[ch];
        const float* rb = (bb >= 0) ? raw + (bb * E1 + ey) * RP1 : ra;
        bool mul = (bb >= 0);
        float s = 0.f;
#pragma unroll
        for (int i = 0; i < 17; i++) {
            float v = ra[i];
            if (mul) v *= rb[i];
            s += v;
        }
        float* hrow = hs + (ch * E1 + ey) * HP1;
        hrow[0] = s;
#pragma unroll
        for (int x = 1; x < T1; x++) {
            float vl = ra[x + 16], vt = ra[x - 1];
            if (mul) { vl *= rb[x + 16]; vt *= rb[x - 1]; }
            s += vl - vt;
            hrow[x] = s;
        }
    }
    __syncthreads();

    // ---- Phase 2: vertical 17-tap box -> out, split in 2 y-halves (1216 tasks) ----
    for (int t = tid; t < NCH * T1 * 2; t += NT1) {
        int col = t & 31;
        int ch  = (t >> 5) % NCH;
        int hf  = (t >> 5) / NCH;          // 0 or 1
        int yb  = hf * 16;                 // local y base
        const float* h0 = hs + ((size_t)ch * E1 + yb) * HP1 + col;
        float s = 0.f;
#pragma unroll
        for (int j = 0; j < 17; j++) s += h0[j * HP1];
        float* o = out + (ch * T1 + yb) * T1 + col;
        o[0] = s;
#pragma unroll
        for (int y = 1; y < 16; y++) {
            s += h0[(y + 16) * HP1] - h0[(y - 1) * HP1];
            o[y * T1] = s;
        }
    }
    __syncthreads();

    // ---- Phase 3: per-pixel 4x4 SPD solve  M x = 1  (1024 pixels, 1/thread) ----
    {
        int k = tid;
        int x = k & 31, y = k >> 5;
        float invN = 1.0f / (float)(wcnt(X0 + x, Wn) * wcnt(Y0 + y, Hn));

        float S[NCH];
#pragma unroll
        for (int c = 0; c < NCH; c++) S[c] = out[(c * T1 + y) * T1 + x];

        float m0 = S[0] * invN, m1 = S[1] * invN, m2 = S[2] * invN, m3 = S[3] * invN;
        float pm = S[4] * invN;
        float ip0 = S[5] * invN, ip1 = S[6] * invN, ip2 = S[7] * invN, ip3 = S[8] * invN;

        float Mm[4][4];
        Mm[0][0] = S[9]  * invN + EPSc;
        Mm[0][1] = Mm[1][0] = S[10] * invN;
        Mm[0][2] = Mm[2][0] = S[11] * invN;
        Mm[0][3] = Mm[3][0] = S[12] * invN;
        Mm[1][1] = S[13] * invN + EPSc;
        Mm[1][2] = Mm[2][1] = S[14] * invN;
        Mm[1][3] = Mm[3][1] = S[15] * invN;
        Mm[2][2] = S[16] * invN + EPSc;
        Mm[2][3] = Mm[3][2] = S[17] * invN;
        Mm[3][3] = S[18] * invN + EPSc;

        float xv[4] = {1.f, 1.f, 1.f, 1.f};
#pragma unroll
        for (int kk = 0; kk < 4; kk++) {
            float inv = 1.0f / Mm[kk][kk];
#pragma unroll
            for (int j = 0; j < 4; j++) if (j > kk) Mm[kk][j] *= inv;
            xv[kk] *= inv;
#pragma unroll
            for (int i = 0; i < 4; i++) if (i > kk) {
                float f = Mm[i][kk];
#pragma unroll
                for (int j = 0; j < 4; j++) if (j > kk) Mm[i][j] -= f * Mm[kk][j];
                xv[i] -= f * xv[kk];
            }
        }
#pragma unroll
        for (int kk = 2; kk >= 0; kk--) {
#pragma unroll
            for (int j = 0; j < 4; j++) if (j > kk) xv[kk] -= Mm[kk][j] * xv[j];
        }

        float ft0 = ip0 - pm * m0;
        float ft1 = ip1 - pm * m1;
        float ft2 = ip2 - pm * m2;
        float ft3 = ip3 - pm * m3;
        float Asum = ft0 * xv[0] + ft1 * xv[1] + ft2 * xv[2] + ft3 * xv[3];
        float msum = m0 + m1 + m2 + m3;
        float bv   = pm - Asum * msum;

        size_t pix = ((size_t)b * Hn + (Y0 + y)) * Wn + (X0 + x);
        g_Ab[pix] = Asum;
        g_Ab[(size_t)Bn * Hn * Wn + pix] = bv;
    }
}

// ---------------------------------------------------------------------------
// Stage 2: fused 2D box of (Asum, b) + final combine.
// Tile 64x64, halo 8 -> extended 80x80. 512 threads.
// SMEM (floats): rawAB 2x80x81 = 12960 ; hsAB 2x80x65 = 10400  -> 93440 B
// ---------------------------------------------------------------------------
#define T2 64
#define E2 80
#define RP2 81
#define HP2 65
#define SZ2_RAW (2 * E2 * RP2)   // 12960
#define SZ2_HS  (2 * E2 * HP2)   // 10400
#define SMEM2_BYTES ((SZ2_RAW + SZ2_HS) * 4)   // 93440
#define YSEG 8                    // 64 cols x 8 segs = 512 threads, 8 rows each

__global__ __launch_bounds__(512) void k_stage2(const float* __restrict__ I,
                                                float* __restrict__ q) {
    extern __shared__ float sm[];
    float* raw = sm;
    float* hsb = sm + SZ2_RAW;

    int b  = blockIdx.z;
    int X0 = blockIdx.x * T2, Y0 = blockIdx.y * T2;
    int tid = threadIdx.x;
    const size_t PL = (size_t)Bn * Hn * Wn;

    // ---- Phase 0: load A,b halo tiles ----
    for (int i = tid; i < 2 * E2 * E2; i += 512) {
        int pl = i / (E2 * E2);
        int r  = i % (E2 * E2);
        int ey = r / E2, ex = r % E2;
        int gy = Y0 - Rr + ey, gx = X0 - Rr + ex;
        float v = 0.f;
        if (gx >= 0 && gx < Wn && gy >= 0 && gy < Hn)
            v = g_Ab[(size_t)pl * PL + ((size_t)b * Hn + gy) * Wn + gx];
        raw[(pl * E2 + ey) * RP2 + ex] = v;
    }
    __syncthreads();

    // ---- Phase 1: horizontal box (2 ch x 80 rows = 160 tasks) ----
    for (int t = tid; t < 2 * E2; t += 512) {
        int ey = t % E2, ch = t / E2;
        const float* ra = raw + (ch * E2 + ey) * RP2;
        float s = 0.f;
#pragma unroll
        for (int i = 0; i < 17; i++) s += ra[i];
        float* hrow = hsb + (ch * E2 + ey) * HP2;
        hrow[0] = s;
#pragma unroll 4
        for (int x = 1; x < T2; x++) {
            s += ra[x + 16] - ra[x - 1];
            hrow[x] = s;
        }
    }
    __syncthreads();

    // ---- Phase 2: vertical box + combine, thread = (col, y-segment) ----
    {
        int col = tid & 63;
        int seg = tid >> 6;          // 0..7
        int ys  = seg * YSEG;        // local y start
        const float* hA = hsb + col;
        const float* hB = hsb + (size_t)E2 * HP2 + col;

        float SA = 0.f, SB = 0.f;
#pragma unroll
        for (int j = 0; j < 17; j++) {
            SA += hA[(ys + j) * HP2];
            SB += hB[(ys + j) * HP2];
        }
        int gx = X0 + col;
        int cntx = wcnt(gx, Wn);
        const float* Ib = I + ((size_t)b * Cn) * Hn * Wn;

#pragma unroll
        for (int yy = 0; yy < YSEG; yy++) {
            int gy = Y0 + ys + yy;
            float invN = 1.0f / (float)(wcnt(gy, Hn) * cntx);
            size_t row = (size_t)gy * Wn + gx;
            float isum = Ib[row]
                       + Ib[(size_t)Hn * Wn + row]
                       + Ib[(size_t)2 * Hn * Wn + row]
                       + Ib[(size_t)3 * Hn * Wn + row];
            q[((size_t)b * Hn + gy) * Wn + gx] = (SA * invN) * isum + SB * invN;

            if (yy < YSEG - 1) {
                int lead = ys + yy + 17, trail = ys + yy;
                SA += hA[lead * HP2] - hA[trail * HP2];
                SB += hB[lead * HP2] - hB[trail * HP2];
            }
        }
    }
}

extern "C" void kernel_launch(void* const* d_in, const int* in_sizes, int n_in,
                              void* d_out, int out_size) {
    const float* I = (const float*)d_in[0];
    const float* p = (const float*)d_in[1];
    float* q = (float*)d_out;

    static bool attr_done = false;
    if (!attr_done) {
        cudaFuncSetAttribute(k_stage1, cudaFuncAttributeMaxDynamicSharedMemorySize, SMEM1_BYTES);
        cudaFuncSetAttribute(k_stage2, cudaFuncAttributeMaxDynamicSharedMemorySize, SMEM2_BYTES);
        attr_done = true;
    }

    k_stage1<<<dim3(Wn / T1, Hn / T1, Bn), NT1, SMEM1_BYTES>>>(I, p);
    k_stage2<<<dim3(Wn / T2, Hn / T2, Bn), 512, SMEM2_BYTES>>>(I, q);
}

// round 9
// speedup vs baseline: 1.4799x; 1.4799x over previous
#include <cuda_runtime.h>
#include <cstddef>

#define Bn 8
#define Cn 4
#define Hn 768
#define Wn 768
#define Rr 8
#define NCH 19
#define EPSc 1e-4f

// A-sum and b intermediate (only 2 channels survive stage 1)
__device__ float g_Ab[(size_t)2 * Bn * Hn * Wn];

// channel -> (planeA, planeB); plane 4 = p, 0..3 = I_c, B=-1 -> identity
__constant__ int c_chA[NCH] = {0,1,2,3, 4, 4,4,4,4, 0,0,0,0,1,1,1,2,2,3};
__constant__ int c_chB[NCH] = {-1,-1,-1,-1, -1, 0,1,2,3, 0,1,2,3,1,2,3,2,3,3};

__device__ __forceinline__ int wcnt(int t, int L) {
    int lo = t - Rr; if (lo < 0) lo = 0;
    int hi = t + Rr; if (hi > L - 1) hi = L - 1;
    return hi - lo + 1;
}

// ---------------------------------------------------------------------------
// Stage 1: fused products + 2D box + per-pixel 4x4 SPD solve.
// Tile 32x16 (WxH), halo 8 -> extended 48x32. 512 threads, 2 CTAs/SM.
// Channels processed in 2 groups (9 + 10) sharing one 10-ch hs buffer.
// SMEM (floats):
//   hs  [0, 10560)          : 10 ch x 32 rows x 33
//   raw [10560, 18400)      : 5 planes x 32 rows x 49
//   out [18400, 28128)      : 19 ch x 16 x 32
// total 28128 floats = 112512 B  -> 2 CTAs/SM (225 KB / 228 KB)
// ---------------------------------------------------------------------------
#define T1W 32
#define T1H 16
#define EW1 48
#define EH1 32
#define RPW 49
#define HP1 33
#define SZ1_HS  (10 * EH1 * HP1)        // 10560
#define SZ1_RAW (5 * EH1 * RPW)         // 7840
#define SZ1_OUT (NCH * T1H * T1W)       // 9728
#define SMEM1_BYTES ((SZ1_HS + SZ1_RAW + SZ1_OUT) * 4)   // 112512

__global__ __launch_bounds__(512, 2) void k_stage1(const float* __restrict__ I,
                                                   const float* __restrict__ p) {
    extern __shared__ float sm[];
    float* hs  = sm;
    float* raw = sm + SZ1_HS;
    float* out = sm + SZ1_HS + SZ1_RAW;

    int b  = blockIdx.z;
    int X0 = blockIdx.x * T1W, Y0 = blockIdx.y * T1H;
    int tid = threadIdx.x;

    // ---- Phase 0: load raw halo tile (5 planes, zero-padded) ----
#pragma unroll
    for (int pl = 0; pl < 5; pl++) {
        const float* src = (pl < 4) ? I + (((size_t)b * Cn + pl) * Hn) * Wn
                                    : p + ((size_t)b * Hn) * Wn;
        for (int j = tid; j < EH1 * EW1; j += 512) {
            int ey = j / EW1, ex = j % EW1;
            int gy = Y0 - Rr + ey, gx = X0 - Rr + ex;
            float v = 0.f;
            if (gx >= 0 && gx < Wn && gy >= 0 && gy < Hn)
                v = src[(size_t)gy * Wn + gx];
            raw[(pl * EH1 + ey) * RPW + ex] = v;
        }
    }
    __syncthreads();

    // ---- Channel groups: G0 = ch 0..8 (9), G1 = ch 9..18 (10) ----
#pragma unroll
    for (int g = 0; g < 2; g++) {
        int base = g ? 9 : 0;
        int cnt  = g ? 10 : 9;

        // -- P1: horizontal 17-tap box; task = (ch, row, x-half of 16) --
        for (int t = tid; t < cnt * EH1 * 2; t += 512) {
            int c   = t >> 6;              // local ch
            int rem = t & 63;
            int row = rem >> 1;
            int x0  = (rem & 1) << 4;      // 0 or 16
            const float* ra = raw + (c_chA[base + c] * EH1 + row) * RPW + x0;
            int bb = c_chB[base + c];
            const float* rb = (bb >= 0) ? raw + (bb * EH1 + row) * RPW + x0 : ra;
            bool mul = (bb >= 0);

            float s = 0.f;
#pragma unroll
            for (int i = 0; i < 17; i++) {
                float v = ra[i];
                if (mul) v *= rb[i];
                s += v;
            }
            float* hrow = hs + (c * EH1 + row) * HP1 + x0;
            hrow[0] = s;
#pragma unroll
            for (int j = 1; j < 16; j++) {
                float vl = ra[j + 16], vt = ra[j - 1];
                if (mul) { vl *= rb[j + 16]; vt *= rb[j - 1]; }
                s += vl - vt;
                hrow[j] = s;
            }
        }
        __syncthreads();

        // -- P2: vertical 17-tap box; task = (ch, col), slide 16 rows --
        for (int t = tid; t < cnt * T1W; t += 512) {
            int c = t >> 5, col = t & 31;
            const float* h0 = hs + (size_t)(c * EH1) * HP1 + col;
            float s = 0.f;
#pragma unroll
            for (int j = 0; j < 17; j++) s += h0[j * HP1];
            float* o = out + ((base + c) * T1H) * T1W + col;
            o[0] = s;
#pragma unroll
            for (int y = 1; y < T1H; y++) {
                s += h0[(y + 16) * HP1] - h0[(y - 1) * HP1];
                o[y * T1W] = s;
            }
        }
        __syncthreads();
    }

    // ---- Phase 3: per-pixel 4x4 SPD solve  M x = 1  (512 px, 1/thread) ----
    {
        int x = tid & 31, y = tid >> 5;   // y in 0..15
        float invN = 1.0f / (float)(wcnt(X0 + x, Wn) * wcnt(Y0 + y, Hn));

        float S[NCH];
#pragma unroll
        for (int c = 0; c < NCH; c++) S[c] = out[(c * T1H + y) * T1W + x];

        float m0 = S[0] * invN, m1 = S[1] * invN, m2 = S[2] * invN, m3 = S[3] * invN;
        float pm = S[4] * invN;
        float ip0 = S[5] * invN, ip1 = S[6] * invN, ip2 = S[7] * invN, ip3 = S[8] * invN;

        float Mm[4][4];
        Mm[0][0] = S[9]  * invN + EPSc;
        Mm[0][1] = Mm[1][0] = S[10] * invN;
        Mm[0][2] = Mm[2][0] = S[11] * invN;
        Mm[0][3] = Mm[3][0] = S[12] * invN;
        Mm[1][1] = S[13] * invN + EPSc;
        Mm[1][2] = Mm[2][1] = S[14] * invN;
        Mm[1][3] = Mm[3][1] = S[15] * invN;
        Mm[2][2] = S[16] * invN + EPSc;
        Mm[2][3] = Mm[3][2] = S[17] * invN;
        Mm[3][3] = S[18] * invN + EPSc;

        float xv[4] = {1.f, 1.f, 1.f, 1.f};
#pragma unroll
        for (int kk = 0; kk < 4; kk++) {
            float inv = 1.0f / Mm[kk][kk];
#pragma unroll
            for (int j = 0; j < 4; j++) if (j > kk) Mm[kk][j] *= inv;
            xv[kk] *= inv;
#pragma unroll
            for (int i = 0; i < 4; i++) if (i > kk) {
                float f = Mm[i][kk];
#pragma unroll
                for (int j = 0; j < 4; j++) if (j > kk) Mm[i][j] -= f * Mm[kk][j];
                xv[i] -= f * xv[kk];
            }
        }
#pragma unroll
        for (int kk = 2; kk >= 0; kk--) {
#pragma unroll
            for (int j = 0; j < 4; j++) if (j > kk) xv[kk] -= Mm[kk][j] * xv[j];
        }

        float ft0 = ip0 - pm * m0;
        float ft1 = ip1 - pm * m1;
        float ft2 = ip2 - pm * m2;
        float ft3 = ip3 - pm * m3;
        float Asum = ft0 * xv[0] + ft1 * xv[1] + ft2 * xv[2] + ft3 * xv[3];
        float msum = m0 + m1 + m2 + m3;
        float bv   = pm - Asum * msum;

        size_t pix = ((size_t)b * Hn + (Y0 + y)) * Wn + (X0 + x);
        g_Ab[pix] = Asum;
        g_Ab[(size_t)Bn * Hn * Wn + pix] = bv;
    }
}

// ---------------------------------------------------------------------------
// Stage 2: fused 2D box of (Asum, b) + final combine. (unchanged, 57us)
// Tile 64x64, halo 8 -> extended 80x80. 512 threads.
// ---------------------------------------------------------------------------
#define T2 64
#define E2 80
#define RP2 81
#define HP2 65
#define SZ2_RAW (2 * E2 * RP2)   // 12960
#define SZ2_HS  (2 * E2 * HP2)   // 10400
#define SMEM2_BYTES ((SZ2_RAW + SZ2_HS) * 4)   // 93440
#define YSEG 8

__global__ __launch_bounds__(512) void k_stage2(const float* __restrict__ I,
                                                float* __restrict__ q) {
    extern __shared__ float sm[];
    float* raw = sm;
    float* hsb = sm + SZ2_RAW;

    int b  = blockIdx.z;
    int X0 = blockIdx.x * T2, Y0 = blockIdx.y * T2;
    int tid = threadIdx.x;
    const size_t PL = (size_t)Bn * Hn * Wn;

    for (int i = tid; i < 2 * E2 * E2; i += 512) {
        int pl = i / (E2 * E2);
        int r  = i % (E2 * E2);
        int ey = r / E2, ex = r % E2;
        int gy = Y0 - Rr + ey, gx = X0 - Rr + ex;
        float v = 0.f;
        if (gx >= 0 && gx < Wn && gy >= 0 && gy < Hn)
            v = g_Ab[(size_t)pl * PL + ((size_t)b * Hn + gy) * Wn + gx];
        raw[(pl * E2 + ey) * RP2 + ex] = v;
    }
    __syncthreads();

    for (int t = tid; t < 2 * E2; t += 512) {
        int ey = t % E2, ch = t / E2;
        const float* ra = raw + (ch * E2 + ey) * RP2;
        float s = 0.f;
#pragma unroll
        for (int i = 0; i < 17; i++) s += ra[i];
        float* hrow = hsb + (ch * E2 + ey) * HP2;
        hrow[0] = s;
#pragma unroll 4
        for (int x = 1; x < T2; x++) {
            s += ra[x + 16] - ra[x - 1];
            hrow[x] = s;
        }
    }
    __syncthreads();

    {
        int col = tid & 63;
        int seg = tid >> 6;
        int ys  = seg * YSEG;
        const float* hA = hsb + col;
        const float* hB = hsb + (size_t)E2 * HP2 + col;

        float SA = 0.f, SB = 0.f;
#pragma unroll
        for (int j = 0; j < 17; j++) {
            SA += hA[(ys + j) * HP2];
            SB += hB[(ys + j) * HP2];
        }
        int gx = X0 + col;
        int cntx = wcnt(gx, Wn);
        const float* Ib = I + ((size_t)b * Cn) * Hn * Wn;

#pragma unroll
        for (int yy = 0; yy < YSEG; yy++) {
            int gy = Y0 + ys + yy;
            float invN = 1.0f / (float)(wcnt(gy, Hn) * cntx);
            size_t row = (size_t)gy * Wn + gx;
            float isum = Ib[row]
                       + Ib[(size_t)Hn * Wn + row]
                       + Ib[(size_t)2 * Hn * Wn + row]
                       + Ib[(size_t)3 * Hn * Wn + row];
            q[((size_t)b * Hn + gy) * Wn + gx] = (SA * invN) * isum + SB * invN;

            if (yy < YSEG - 1) {
                int lead = ys + yy + 17, trail = ys + yy;
                SA += hA[lead * HP2] - hA[trail * HP2];
                SB += hB[lead * HP2] - hB[trail * HP2];
            }
        }
    }
}

extern "C" void kernel_launch(void* const* d_in, const int* in_sizes, int n_in,
                              void* d_out, int out_size) {
    const float* I = (const float*)d_in[0];
    const float* p = (const float*)d_in[1];
    float* q = (float*)d_out;

    static bool attr_done = false;
    if (!attr_done) {
        cudaFuncSetAttribute(k_stage1, cudaFuncAttributeMaxDynamicSharedMemorySize, SMEM1_BYTES);
        cudaFuncSetAttribute(k_stage2, cudaFuncAttributeMaxDynamicSharedMemorySize, SMEM2_BYTES);
        attr_done = true;
    }

    k_stage1<<<dim3(Wn / T1W, Hn / T1H, Bn), 512, SMEM1_BYTES>>>(I, p);
    k_stage2<<<dim3(Wn / T2, Hn / T2, Bn), 512, SMEM2_BYTES>>>(I, q);
}

// round 10
// speedup vs baseline: 1.7487x; 1.1817x over previous
#include <cuda_runtime.h>
#include <cstddef>

#define Bn 8
#define Cn 4
#define Hn 768
#define Wn 768
#define Rr 8
#define NCH 19
#define EPSc 1e-4f

// A-sum and b intermediate (only 2 channels survive stage 1)
__device__ float g_Ab[(size_t)2 * Bn * Hn * Wn];

// product channels 5..18 -> (planeA, planeB); plane 4 = p, 0..3 = I_c
__constant__ int c_pA[NCH] = {0,1,2,3, 4, 4,4,4,4, 0,0,0,0,1,1,1,2,2,3};
__constant__ int c_pB[NCH] = {0,1,2,3, 4, 0,1,2,3, 0,1,2,3,1,2,3,2,3,3};

__device__ __forceinline__ int wcnt(int t, int L) {
    int lo = t - Rr; if (lo < 0) lo = 0;
    int hi = t + Rr; if (hi > L - 1) hi = L - 1;
    return hi - lo + 1;
}

// ---------------------------------------------------------------------------
// Stage 1: fused products + 2D box + per-pixel 4x4 SPD solve.
// Tile 32x16 (WxH), halo 8 -> extended 48x32. 512 threads, 2 CTAs/SM.
// Channels in 2 groups (9 + 10) sharing one 10-ch hs buffer.
// SMEM (floats): hs 10x32x33 = 10560 ; raw 5x32x49 = 7840 ; out 19x16x32 = 9728
// total 28128 floats = 112512 B -> 2 CTAs/SM
// ---------------------------------------------------------------------------
#define T1W 32
#define T1H 16
#define EW1 48
#define EH1 32
#define RPW 49
#define HP1 33
#define SZ1_HS  (10 * EH1 * HP1)
#define SZ1_RAW (5 * EH1 * RPW)
#define SZ1_OUT (NCH * T1H * T1W)
#define SMEM1_BYTES ((SZ1_HS + SZ1_RAW + SZ1_OUT) * 4)

__global__ __launch_bounds__(512, 2) void k_stage1(const float* __restrict__ I,
                                                   const float* __restrict__ p) {
    extern __shared__ float sm[];
    float* hs  = sm;
    float* raw = sm + SZ1_HS;
    float* out = sm + SZ1_HS + SZ1_RAW;

    int b  = blockIdx.z;
    int X0 = blockIdx.x * T1W, Y0 = blockIdx.y * T1H;
    int tid = threadIdx.x;
    const size_t HW = (size_t)Hn * Wn;

    // ---- Phase 0: load raw halo tile (5 planes, zero-padded, float4 path) ----
    {
        bool intx = (X0 >= Rr) && (X0 + T1W + Rr <= Wn);   // all 48 ext cols in-bounds
        for (int i = tid; i < 5 * EH1 * 12; i += 512) {
            int pl  = i / (EH1 * 12);
            int rem = i - pl * (EH1 * 12);
            int ey  = rem / 12;
            int ex4 = rem - ey * 12;
            int gy  = Y0 - Rr + ey;
            int gx0 = X0 - Rr + ex4 * 4;
            const float* src = (pl < 4) ? I + ((size_t)b * Cn + pl) * HW
                                        : p + (size_t)b * HW;
            float4 v = make_float4(0.f, 0.f, 0.f, 0.f);
            if ((unsigned)gy < (unsigned)Hn) {
                if (intx) {
                    v = *reinterpret_cast<const float4*>(src + (size_t)gy * Wn + gx0);
                } else {
                    const float* r = src + (size_t)gy * Wn;
                    if ((unsigned)(gx0 + 0) < (unsigned)Wn) v.x = r[gx0 + 0];
                    if ((unsigned)(gx0 + 1) < (unsigned)Wn) v.y = r[gx0 + 1];
                    if ((unsigned)(gx0 + 2) < (unsigned)Wn) v.z = r[gx0 + 2];
                    if ((unsigned)(gx0 + 3) < (unsigned)Wn) v.w = r[gx0 + 3];
                }
            }
            float* d = raw + (pl * EH1 + ey) * RPW + ex4 * 4;
            d[0] = v.x; d[1] = v.y; d[2] = v.z; d[3] = v.w;
        }
    }
    __syncthreads();

    // ---- Channel groups: G0 = ch 0..8 (5 identity + 4 product), G1 = ch 9..18 ----
#pragma unroll
    for (int g = 0; g < 2; g++) {
        int base = g ? 9 : 0;
        int cnt  = g ? 10 : 9;
        int nIdent = g ? 0 : 5;                 // identity tasks: 5 ch x 64
        int nTasks = cnt * 64;

        // -- P1: horizontal 17-tap box; task = (ch, row, x-half of 16) --
        for (int t = tid; t < nTasks; t += 512) {
            if (t < nIdent * 64) {
                // identity channel: box of raw plane itself
                int pl  = t >> 6;
                int rem = t & 63;
                int row = rem >> 1;
                int x0  = (rem & 1) << 4;
                const float* ra = raw + (pl * EH1 + row) * RPW + x0;
                float* hrow = hs + (pl * EH1 + row) * HP1 + x0;
                float s = 0.f;
#pragma unroll
                for (int i = 0; i < 17; i++) s += ra[i];
                hrow[0] = s;
#pragma unroll
                for (int j = 1; j < 16; j++) {
                    s += ra[j + 16] - ra[j - 1];
                    hrow[j] = s;
                }
            } else {
                // product channel
                int tt  = t - nIdent * 64;
                int c   = base + nIdent + (tt >> 6);   // global ch 5..18
                int rem = tt & 63;
                int row = rem >> 1;
                int x0  = (rem & 1) << 4;
                const float* ra = raw + (c_pA[c] * EH1 + row) * RPW + x0;
                const float* rb = raw + (c_pB[c] * EH1 + row) * RPW + x0;
                float* hrow = hs + ((c - base) * EH1 + row) * HP1 + x0;
                float s = 0.f;
#pragma unroll
                for (int i = 0; i < 17; i++) s = fmaf(ra[i], rb[i], s);
                hrow[0] = s;
#pragma unroll
                for (int j = 1; j < 16; j++) {
                    s = fmaf(ra[j + 16], rb[j + 16], s);
                    s = fmaf(-ra[j - 1], rb[j - 1], s);
                    hrow[j] = s;
                }
            }
        }
        __syncthreads();

        // -- P2: vertical 17-tap box; task = (ch, col), slide 16 rows --
        for (int t = tid; t < cnt * T1W; t += 512) {
            int c = t >> 5, col = t & 31;
            const float* h0 = hs + (size_t)(c * EH1) * HP1 + col;
            float s = 0.f;
#pragma unroll
            for (int j = 0; j < 17; j++) s += h0[j * HP1];
            float* o = out + ((base + c) * T1H) * T1W + col;
            o[0] = s;
#pragma unroll
            for (int y = 1; y < T1H; y++) {
                s += h0[(y + 16) * HP1] - h0[(y - 1) * HP1];
                o[y * T1W] = s;
            }
        }
        __syncthreads();
    }

    // ---- Phase 3: per-pixel 4x4 SPD solve  M x = 1  (512 px, 1/thread) ----
    {
        int x = tid & 31, y = tid >> 5;
        float invN = 1.0f / (float)(wcnt(X0 + x, Wn) * wcnt(Y0 + y, Hn));

        float S[NCH];
#pragma unroll
        for (int c = 0; c < NCH; c++) S[c] = out[(c * T1H + y) * T1W + x];

        float m0 = S[0] * invN, m1 = S[1] * invN, m2 = S[2] * invN, m3 = S[3] * invN;
        float pm = S[4] * invN;
        float ip0 = S[5] * invN, ip1 = S[6] * invN, ip2 = S[7] * invN, ip3 = S[8] * invN;

        float Mm[4][4];
        Mm[0][0] = S[9]  * invN + EPSc;
        Mm[0][1] = Mm[1][0] = S[10] * invN;
        Mm[0][2] = Mm[2][0] = S[11] * invN;
        Mm[0][3] = Mm[3][0] = S[12] * invN;
        Mm[1][1] = S[13] * invN + EPSc;
        Mm[1][2] = Mm[2][1] = S[14] * invN;
        Mm[1][3] = Mm[3][1] = S[15] * invN;
        Mm[2][2] = S[16] * invN + EPSc;
        Mm[2][3] = Mm[3][2] = S[17] * invN;
        Mm[3][3] = S[18] * invN + EPSc;

        float xv[4] = {1.f, 1.f, 1.f, 1.f};
#pragma unroll
        for (int kk = 0; kk < 4; kk++) {
            float inv = 1.0f / Mm[kk][kk];
#pragma unroll
            for (int j = 0; j < 4; j++) if (j > kk) Mm[kk][j] *= inv;
            xv[kk] *= inv;
#pragma unroll
            for (int i = 0; i < 4; i++) if (i > kk) {
                float f = Mm[i][kk];
#pragma unroll
                for (int j = 0; j < 4; j++) if (j > kk) Mm[i][j] -= f * Mm[kk][j];
                xv[i] -= f * xv[kk];
            }
        }
#pragma unroll
        for (int kk = 2; kk >= 0; kk--) {
#pragma unroll
            for (int j = 0; j < 4; j++) if (j > kk) xv[kk] -= Mm[kk][j] * xv[j];
        }

        float ft0 = ip0 - pm * m0;
        float ft1 = ip1 - pm * m1;
        float ft2 = ip2 - pm * m2;
        float ft3 = ip3 - pm * m3;
        float Asum = ft0 * xv[0] + ft1 * xv[1] + ft2 * xv[2] + ft3 * xv[3];
        float msum = m0 + m1 + m2 + m3;
        float bv   = pm - Asum * msum;

        size_t pix = ((size_t)b * Hn + (Y0 + y)) * Wn + (X0 + x);
        g_Ab[pix] = Asum;
        g_Ab[(size_t)Bn * Hn * Wn + pix] = bv;
    }
}

// ---------------------------------------------------------------------------
// Stage 2: fused 2D box of (Asum, b) + final combine. (unchanged)
// ---------------------------------------------------------------------------
#define T2 64
#define E2 80
#define RP2 81
#define HP2 65
#define SZ2_RAW (2 * E2 * RP2)
#define SZ2_HS  (2 * E2 * HP2)
#define SMEM2_BYTES ((SZ2_RAW + SZ2_HS) * 4)
#define YSEG 8

__global__ __launch_bounds__(512) void k_stage2(const float* __restrict__ I,
                                                float* __restrict__ q) {
    extern __shared__ float sm[];
    float* raw = sm;
    float* hsb = sm + SZ2_RAW;

    int b  = blockIdx.z;
    int X0 = blockIdx.x * T2, Y0 = blockIdx.y * T2;
    int tid = threadIdx.x;
    const size_t PL = (size_t)Bn * Hn * Wn;

    for (int i = tid; i < 2 * E2 * E2; i += 512) {
        int pl = i / (E2 * E2);
        int r  = i % (E2 * E2);
        int ey = r / E2, ex = r % E2;
        int gy = Y0 - Rr + ey, gx = X0 - Rr + ex;
        float v = 0.f;
        if (gx >= 0 && gx < Wn && gy >= 0 && gy < Hn)
            v = g_Ab[(size_t)pl * PL + ((size_t)b * Hn + gy) * Wn + gx];
        raw[(pl * E2 + ey) * RP2 + ex] = v;
    }
    __syncthreads();

    for (int t = tid; t < 2 * E2; t += 512) {
        int ey = t % E2, ch = t / E2;
        const float* ra = raw + (ch * E2 + ey) * RP2;
        float s = 0.f;
#pragma unroll
        for (int i = 0; i < 17; i++) s += ra[i];
        float* hrow = hsb + (ch * E2 + ey) * HP2;
        hrow[0] = s;
#pragma unroll 4
        for (int x = 1; x < T2; x++) {
            s += ra[x + 16] - ra[x - 1];
            hrow[x] = s;
        }
    }
    __syncthreads();

    {
        int col = tid & 63;
        int seg = tid >> 6;
        int ys  = seg * YSEG;
        const float* hA = hsb + col;
        const float* hB = hsb + (size_t)E2 * HP2 + col;

        float SA = 0.f, SB = 0.f;
#pragma unroll
        for (int j = 0; j < 17; j++) {
            SA += hA[(ys + j) * HP2];
            SB += hB[(ys + j) * HP2];
        }
        int gx = X0 + col;
        int cntx = wcnt(gx, Wn);
        const float* Ib = I + ((size_t)b * Cn) * Hn * Wn;

#pragma unroll
        for (int yy = 0; yy < YSEG; yy++) {
            int gy = Y0 + ys + yy;
            float invN = 1.0f / (float)(wcnt(gy, Hn) * cntx);
            size_t row = (size_t)gy * Wn + gx;
            float isum = Ib[row]
                       + Ib[(size_t)Hn * Wn + row]
                       + Ib[(size_t)2 * Hn * Wn + row]
                       + Ib[(size_t)3 * Hn * Wn + row];
            q[((size_t)b * Hn + gy) * Wn + gx] = (SA * invN) * isum + SB * invN;

            if (yy < YSEG - 1) {
                int lead = ys + yy + 17, trail = ys + yy;
                SA += hA[lead * HP2] - hA[trail * HP2];
                SB += hB[lead * HP2] - hB[trail * HP2];
            }
        }
    }
}

extern "C" void kernel_launch(void* const* d_in, const int* in_sizes, int n_in,
                              void* d_out, int out_size) {
    const float* I = (const float*)d_in[0];
    const float* p = (const float*)d_in[1];
    float* q = (float*)d_out;

    static bool attr_done = false;
    if (!attr_done) {
        cudaFuncSetAttribute(k_stage1, cudaFuncAttributeMaxDynamicSharedMemorySize, SMEM1_BYTES);
        cudaFuncSetAttribute(k_stage2, cudaFuncAttributeMaxDynamicSharedMemorySize, SMEM2_BYTES);
        attr_done = true;
    }

    k_stage1<<<dim3(Wn / T1W, Hn / T1H, Bn), 512, SMEM1_BYTES>>>(I, p);
    k_stage2<<<dim3(Wn / T2, Hn / T2, Bn), 512, SMEM2_BYTES>>>(I, q);
}

// round 11
// speedup vs baseline: 1.9357x; 1.1070x over previous
#include <cuda_runtime.h>
#include <cstddef>

#define Bn 8
#define Cn 4
#define Hn 768
#define Wn 768
#define Rr 8
#define NCH 19
#define EPSc 1e-4f

// A-sum and b intermediate (only 2 channels survive stage 1)
__device__ float g_Ab[(size_t)2 * Bn * Hn * Wn];

// product channels 5..18 -> (planeA, planeB); plane 4 = p, 0..3 = I_c
__constant__ int c_pA[NCH] = {0,1,2,3, 4, 4,4,4,4, 0,0,0,0,1,1,1,2,2,3};
__constant__ int c_pB[NCH] = {0,1,2,3, 4, 0,1,2,3, 0,1,2,3,1,2,3,2,3,3};

__device__ __forceinline__ int wcnt(int t, int L) {
    int lo = t - Rr; if (lo < 0) lo = 0;
    int hi = t + Rr; if (hi > L - 1) hi = L - 1;
    return hi - lo + 1;
}

// fast reciprocal (rel err ~1e-7, tolerance is 1e-3)
__device__ __forceinline__ float frcp(float x) {
    float r;
    asm("rcp.approx.f32 %0, %1;" : "=f"(r) : "f"(x));
    return r;
}

// ---------------------------------------------------------------------------
// Stage 1: fused products + 2D box + per-pixel 4x4 SPD solve.
// Tile 32x16 (WxH), halo 8 -> extended 48x32. 512 threads, 2 CTAs/SM.
// Channels in 2 groups (9 + 10) sharing one 10-ch hs buffer.
// SMEM (floats): hs 10x32x33 = 10560 ; raw 5x32x49 = 7840 ; out 19x16x32 = 9728
// total 28128 floats = 112512 B -> 2 CTAs/SM
// ---------------------------------------------------------------------------
#define T1W 32
#define T1H 16
#define EW1 48
#define EH1 32
#define RPW 49
#define HP1 33
#define SZ1_HS  (10 * EH1 * HP1)
#define SZ1_RAW (5 * EH1 * RPW)
#define SZ1_OUT (NCH * T1H * T1W)
#define SMEM1_BYTES ((SZ1_HS + SZ1_RAW + SZ1_OUT) * 4)

__global__ __launch_bounds__(512, 2) void k_stage1(const float* __restrict__ I,
                                                   const float* __restrict__ p) {
    extern __shared__ float sm[];
    float* hs  = sm;
    float* raw = sm + SZ1_HS;
    float* out = sm + SZ1_HS + SZ1_RAW;

    int b  = blockIdx.z;
    int X0 = blockIdx.x * T1W, Y0 = blockIdx.y * T1H;
    int tid = threadIdx.x;
    const size_t HW = (size_t)Hn * Wn;

    // ---- Phase 0: load raw halo tile (5 planes, zero-padded, float4 path) ----
    {
        bool intx = (X0 >= Rr) && (X0 + T1W + Rr <= Wn);
        for (int i = tid; i < 5 * EH1 * 12; i += 512) {
            int pl  = i / (EH1 * 12);
            int rem = i - pl * (EH1 * 12);
            int ey  = rem / 12;
            int ex4 = rem - ey * 12;
            int gy  = Y0 - Rr + ey;
            int gx0 = X0 - Rr + ex4 * 4;
            const float* src = (pl < 4) ? I + ((size_t)b * Cn + pl) * HW
                                        : p + (size_t)b * HW;
            float4 v = make_float4(0.f, 0.f, 0.f, 0.f);
            if ((unsigned)gy < (unsigned)Hn) {
                if (intx) {
                    v = *reinterpret_cast<const float4*>(src + (size_t)gy * Wn + gx0);
                } else {
                    const float* r = src + (size_t)gy * Wn;
                    if ((unsigned)(gx0 + 0) < (unsigned)Wn) v.x = r[gx0 + 0];
                    if ((unsigned)(gx0 + 1) < (unsigned)Wn) v.y = r[gx0 + 1];
                    if ((unsigned)(gx0 + 2) < (unsigned)Wn) v.z = r[gx0 + 2];
                    if ((unsigned)(gx0 + 3) < (unsigned)Wn) v.w = r[gx0 + 3];
                }
            }
            float* d = raw + (pl * EH1 + ey) * RPW + ex4 * 4;
            d[0] = v.x; d[1] = v.y; d[2] = v.z; d[3] = v.w;
        }
    }
    __syncthreads();

    // ---- Channel groups: G0 = ch 0..8 (5 identity + 4 product), G1 = ch 9..18 ----
#pragma unroll
    for (int g = 0; g < 2; g++) {
        const int base = g ? 9 : 0;
        const int cnt  = g ? 10 : 9;
        const int nIdent = g ? 0 : 5;
        const int nTasks = cnt * 64;

        // -- P1: horizontal 17-tap box; task = (ch, row, x-half of 16) --
        for (int t = tid; t < nTasks; t += 512) {
            if (t < nIdent * 64) {
                int pl  = t >> 6;
                int rem = t & 63;
                int row = rem >> 1;
                int x0  = (rem & 1) << 4;
                const float* ra = raw + (pl * EH1 + row) * RPW + x0;
                float* hrow = hs + (pl * EH1 + row) * HP1 + x0;
                float s = 0.f;
#pragma unroll
                for (int i = 0; i < 17; i++) s += ra[i];
                hrow[0] = s;
#pragma unroll
                for (int j = 1; j < 16; j++) {
                    s += ra[j + 16] - ra[j - 1];
                    hrow[j] = s;
                }
            } else {
                int tt  = t - nIdent * 64;
                int c   = base + nIdent + (tt >> 6);
                int rem = tt & 63;
                int row = rem >> 1;
                int x0  = (rem & 1) << 4;
                const float* ra = raw + (c_pA[c] * EH1 + row) * RPW + x0;
                const float* rb = raw + (c_pB[c] * EH1 + row) * RPW + x0;
                float* hrow = hs + ((c - base) * EH1 + row) * HP1 + x0;
                float s = 0.f;
#pragma unroll
                for (int i = 0; i < 17; i++) s = fmaf(ra[i], rb[i], s);
                hrow[0] = s;
#pragma unroll
                for (int j = 1; j < 16; j++) {
                    s = fmaf(ra[j + 16], rb[j + 16], s);
                    s = fmaf(-ra[j - 1], rb[j - 1], s);
                    hrow[j] = s;
                }
            }
        }
        __syncthreads();

        // -- P2: vertical 17-tap box, split in 2 y-halves of 8 rows --
        //    task = (half, ch, col): cnt*64 tasks
        for (int t = tid; t < cnt * 64; t += 512) {
            int hf  = (t >= cnt * 32) ? 1 : 0;
            int idx = t - hf * cnt * 32;
            int c   = idx >> 5;
            int col = idx & 31;
            int yb  = hf << 3;
            const float* h0 = hs + ((size_t)c * EH1 + yb) * HP1 + col;
            float s = 0.f;
#pragma unroll
            for (int j = 0; j < 17; j++) s += h0[j * HP1];
            float* o = out + ((base + c) * T1H + yb) * T1W + col;
            o[0] = s;
#pragma unroll
            for (int y = 1; y < 8; y++) {
                s += h0[(y + 16) * HP1] - h0[(y - 1) * HP1];
                o[y * T1W] = s;
            }
        }
        __syncthreads();
    }

    // ---- Phase 3: per-pixel 4x4 SPD solve  M x = 1  (512 px, 1/thread) ----
    {
        int x = tid & 31, y = tid >> 5;
        float invN = frcp((float)(wcnt(X0 + x, Wn) * wcnt(Y0 + y, Hn)));

        float S[NCH];
#pragma unroll
        for (int c = 0; c < NCH; c++) S[c] = out[(c * T1H + y) * T1W + x];

        float m0 = S[0] * invN, m1 = S[1] * invN, m2 = S[2] * invN, m3 = S[3] * invN;
        float pm = S[4] * invN;
        float ip0 = S[5] * invN, ip1 = S[6] * invN, ip2 = S[7] * invN, ip3 = S[8] * invN;

        float Mm[4][4];
        Mm[0][0] = S[9]  * invN + EPSc;
        Mm[0][1] = Mm[1][0] = S[10] * invN;
        Mm[0][2] = Mm[2][0] = S[11] * invN;
        Mm[0][3] = Mm[3][0] = S[12] * invN;
        Mm[1][1] = S[13] * invN + EPSc;
        Mm[1][2] = Mm[2][1] = S[14] * invN;
        Mm[1][3] = Mm[3][1] = S[15] * invN;
        Mm[2][2] = S[16] * invN + EPSc;
        Mm[2][3] = Mm[3][2] = S[17] * invN;
        Mm[3][3] = S[18] * invN + EPSc;

        float xv[4] = {1.f, 1.f, 1.f, 1.f};
#pragma unroll
        for (int kk = 0; kk < 4; kk++) {
            float inv = frcp(Mm[kk][kk]);
#pragma unroll
            for (int j = 0; j < 4; j++) if (j > kk) Mm[kk][j] *= inv;
            xv[kk] *= inv;
#pragma unroll
            for (int i = 0; i < 4; i++) if (i > kk) {
                float f = Mm[i][kk];
#pragma unroll
                for (int j = 0; j < 4; j++) if (j > kk) Mm[i][j] -= f * Mm[kk][j];
                xv[i] -= f * xv[kk];
            }
        }
#pragma unroll
        for (int kk = 2; kk >= 0; kk--) {
#pragma unroll
            for (int j = 0; j < 4; j++) if (j > kk) xv[kk] -= Mm[kk][j] * xv[j];
        }

        float ft0 = ip0 - pm * m0;
        float ft1 = ip1 - pm * m1;
        float ft2 = ip2 - pm * m2;
        float ft3 = ip3 - pm * m3;
        float Asum = ft0 * xv[0] + ft1 * xv[1] + ft2 * xv[2] + ft3 * xv[3];
        float msum = m0 + m1 + m2 + m3;
        float bv   = pm - Asum * msum;

        size_t pix = ((size_t)b * Hn + (Y0 + y)) * Wn + (X0 + x);
        g_Ab[pix] = Asum;
        g_Ab[(size_t)Bn * Hn * Wn + pix] = bv;
    }
}

// ---------------------------------------------------------------------------
// Stage 2: fused 2D box of (Asum, b) + final combine.
// Tile 64x64, halo 8 -> extended 80x80. 512 threads.
// ---------------------------------------------------------------------------
#define T2 64
#define E2 80
#define RP2 81
#define HP2 65
#define SZ2_RAW (2 * E2 * RP2)
#define SZ2_HS  (2 * E2 * HP2)
#define SMEM2_BYTES ((SZ2_RAW + SZ2_HS) * 4)
#define YSEG 8

__global__ __launch_bounds__(512) void k_stage2(const float* __restrict__ I,
                                                float* __restrict__ q) {
    extern __shared__ float sm[];
    float* raw = sm;
    float* hsb = sm + SZ2_RAW;

    int b  = blockIdx.z;
    int X0 = blockIdx.x * T2, Y0 = blockIdx.y * T2;
    int tid = threadIdx.x;
    const size_t PL = (size_t)Bn * Hn * Wn;

    // ---- Phase 0: load A,b halo tiles (float4 interior path) ----
    {
        bool intx = (X0 >= Rr) && (X0 + T2 + Rr <= Wn);
        for (int i = tid; i < 2 * E2 * 20; i += 512) {
            int pl  = i / (E2 * 20);
            int rem = i - pl * (E2 * 20);
            int ey  = rem / 20;
            int ex4 = rem - ey * 20;
            int gy  = Y0 - Rr + ey;
            int gx0 = X0 - Rr + ex4 * 4;
            const float* src = g_Ab + (size_t)pl * PL + (size_t)b * Hn * Wn;
            float4 v = make_float4(0.f, 0.f, 0.f, 0.f);
            if ((unsigned)gy < (unsigned)Hn) {
                if (intx) {
                    v = *reinterpret_cast<const float4*>(src + (size_t)gy * Wn + gx0);
                } else {
                    const float* r = src + (size_t)gy * Wn;
                    if ((unsigned)(gx0 + 0) < (unsigned)Wn) v.x = r[gx0 + 0];
                    if ((unsigned)(gx0 + 1) < (unsigned)Wn) v.y = r[gx0 + 1];
                    if ((unsigned)(gx0 + 2) < (unsigned)Wn) v.z = r[gx0 + 2];
                    if ((unsigned)(gx0 + 3) < (unsigned)Wn) v.w = r[gx0 + 3];
                }
            }
            float* d = raw + (pl * E2 + ey) * RP2 + ex4 * 4;
            d[0] = v.x; d[1] = v.y; d[2] = v.z; d[3] = v.w;
        }
    }
    __syncthreads();

    // ---- Phase 1: horizontal box; task = (ch, row, x-quarter of 16): 640 tasks ----
    for (int t = tid; t < 2 * E2 * 4; t += 512) {
        int ch  = (t >= E2 * 4) ? 1 : 0;
        int rem = t - ch * E2 * 4;
        int ey  = rem >> 2;
        int x0  = (rem & 3) << 4;
        const float* ra = raw + (ch * E2 + ey) * RP2 + x0;
        float s = 0.f;
#pragma unroll
        for (int i = 0; i < 17; i++) s += ra[i];
        float* hrow = hsb + (ch * E2 + ey) * HP2 + x0;
        hrow[0] = s;
#pragma unroll
        for (int x = 1; x < 16; x++) {
            s += ra[x + 16] - ra[x - 1];
            hrow[x] = s;
        }
    }
    __syncthreads();

    // ---- Phase 2: vertical box + combine, thread = (col, y-segment) ----
    {
        int col = tid & 63;
        int seg = tid >> 6;
        int ys  = seg * YSEG;
        const float* hA = hsb + col;
        const float* hB = hsb + (size_t)E2 * HP2 + col;

        float SA = 0.f, SB = 0.f;
#pragma unroll
        for (int j = 0; j < 17; j++) {
            SA += hA[(ys + j) * HP2];
            SB += hB[(ys + j) * HP2];
        }
        int gx = X0 + col;
        int cntx = wcnt(gx, Wn);
        const float* Ib = I + ((size_t)b * Cn) * Hn * Wn;

#pragma unroll
        for (int yy = 0; yy < YSEG; yy++) {
            int gy = Y0 + ys + yy;
            float invN = frcp((float)(wcnt(gy, Hn) * cntx));
            size_t row = (size_t)gy * Wn + gx;
            float isum = Ib[row]
                       + Ib[(size_t)Hn * Wn + row]
                       + Ib[(size_t)2 * Hn * Wn + row]
                       + Ib[(size_t)3 * Hn * Wn + row];
            q[((size_t)b * Hn + gy) * Wn + gx] = (SA * invN) * isum + SB * invN;

            if (yy < YSEG - 1) {
                int lead = ys + yy + 17, trail = ys + yy;
                SA += hA[lead * HP2] - hA[trail * HP2];
                SB += hB[lead * HP2] - hB[trail * HP2];
            }
        }
    }
}

extern "C" void kernel_launch(void* const* d_in, const int* in_sizes, int n_in,
                              void* d_out, int out_size) {
    const float* I = (const float*)d_in[0];
    const float* p = (const float*)d_in[1];
    float* q = (float*)d_out;

    static bool attr_done = false;
    if (!attr_done) {
        cudaFuncSetAttribute(k_stage1, cudaFuncAttributeMaxDynamicSharedMemorySize, SMEM1_BYTES);
        cudaFuncSetAttribute(k_stage2, cudaFuncAttributeMaxDynamicSharedMemorySize, SMEM2_BYTES);
        attr_done = true;
    }

    k_stage1<<<dim3(Wn / T1W, Hn / T1H, Bn), 512, SMEM1_BYTES>>>(I, p);
    k_stage2<<<dim3(Wn / T2, Hn / T2, Bn), 512, SMEM2_BYTES>>>(I, q);
}

// round 12
// speedup vs baseline: 2.1908x; 1.1318x over previous
#include <cuda_runtime.h>
#include <cstddef>

#define Bn 8
#define Cn 4
#define Hn 768
#define Wn 768
#define Rr 8
#define NCH 19
#define EPSc 1e-4f

// A-sum and b intermediate (only 2 channels survive stage 1)
__device__ float g_Ab[(size_t)2 * Bn * Hn * Wn];

__device__ __forceinline__ int wcnt(int t, int L) {
    int lo = t - Rr; if (lo < 0) lo = 0;
    int hi = t + Rr; if (hi > L - 1) hi = L - 1;
    return hi - lo + 1;
}

__device__ __forceinline__ float frcp(float x) {
    float r;
    asm("rcp.approx.f32 %0, %1;" : "=f"(r) : "f"(x));
    return r;
}

// ---------------------------------------------------------------------------
// Stage 1: fused products + 2D box + per-pixel 4x4 SPD solve.
// Tile 32x12 (WxH), halo 8 -> extended 48x28. 512 threads, 2 CTAs/SM.
// P1 computes ALL 19 channels per raw-read: 5 LDS -> 19 running sums in regs.
// SMEM (floats):
//   hs  [0, 17556)              : 19 ch x 28 rows x 33
//   raw/out (aliased) [17556..] : raw 5x28x49 = 6860 ; out 19x12x32 = 7296
// total 24852 floats = 99408 B -> 2 CTAs/SM
// ---------------------------------------------------------------------------
#define T1W 32
#define T1H 12
#define EH1 28
#define RPW 49
#define HP1 33
#define PS1 (EH1 * RPW)        // plane stride in raw = 1372
#define HCH (EH1 * HP1)        // channel stride in hs = 924
#define SZ1_HS  (NCH * HCH)    // 17556
#define SZ1_RO  (NCH * T1H * T1W)   // 7296 (>= raw 6860)
#define SMEM1_BYTES ((SZ1_HS + SZ1_RO) * 4)   // 99408

__global__ __launch_bounds__(512, 2) void k_stage1(const float* __restrict__ I,
                                                   const float* __restrict__ p) {
    extern __shared__ float sm[];
    float* hs  = sm;
    float* raw = sm + SZ1_HS;
    float* out = sm + SZ1_HS;   // NOTE: out aliases raw region start
    // (out region == raw region; raw dead after P1)
    raw = sm + SZ1_HS;
    out = sm + SZ1_HS;

    int b  = blockIdx.z;
    int X0 = blockIdx.x * T1W, Y0 = blockIdx.y * T1H;
    int tid = threadIdx.x;
    const size_t HW = (size_t)Hn * Wn;

    // ---- Phase 0: load raw halo tile (5 planes, zero-padded, float4 path) ----
    {
        bool intx = (X0 >= Rr) && (X0 + T1W + Rr <= Wn);
        for (int i = tid; i < 5 * EH1 * 12; i += 512) {
            int pl  = i / (EH1 * 12);
            int rem = i - pl * (EH1 * 12);
            int ey  = rem / 12;
            int ex4 = rem - ey * 12;
            int gy  = Y0 - Rr + ey;
            int gx0 = X0 - Rr + ex4 * 4;
            const float* src = (pl < 4) ? I + ((size_t)b * Cn + pl) * HW
                                        : p + (size_t)b * HW;
            float4 v = make_float4(0.f, 0.f, 0.f, 0.f);
            if ((unsigned)gy < (unsigned)Hn) {
                if (intx) {
                    v = *reinterpret_cast<const float4*>(src + (size_t)gy * Wn + gx0);
                } else {
                    const float* r = src + (size_t)gy * Wn;
                    if ((unsigned)(gx0 + 0) < (unsigned)Wn) v.x = r[gx0 + 0];
                    if ((unsigned)(gx0 + 1) < (unsigned)Wn) v.y = r[gx0 + 1];
                    if ((unsigned)(gx0 + 2) < (unsigned)Wn) v.z = r[gx0 + 2];
                    if ((unsigned)(gx0 + 3) < (unsigned)Wn) v.w = r[gx0 + 3];
                }
            }
            float* d = raw + (pl * EH1 + ey) * RPW + ex4 * 4;
            d[0] = v.x; d[1] = v.y; d[2] = v.z; d[3] = v.w;
        }
    }
    __syncthreads();

    // ---- P1: horizontal 17-tap box of ALL 19 channels, register sums ----
    // task = (row 0..27, seg 0..7 of 4 px). 224 tasks; warp = 4 rows x 8 segs.
    if (tid < 224) {
        int lane = tid & 31;
        int seg  = lane & 7;
        int row  = (tid >> 5) * 4 + (lane >> 3);
        int x0   = seg * 4;

        const float* r0 = raw + row * RPW + x0;          // plane 0 (I0)
        const float* r1 = r0 + PS1;
        const float* r2 = r0 + 2 * PS1;
        const float* r3 = r0 + 3 * PS1;
        const float* r4 = r0 + 4 * PS1;                  // p

        float s[NCH];
#pragma unroll
        for (int c = 0; c < NCH; c++) s[c] = 0.f;

#pragma unroll
        for (int i = 0; i < 17; i++) {
            float v0 = r0[i], v1 = r1[i], v2 = r2[i], v3 = r3[i], v4 = r4[i];
            s[0] += v0; s[1] += v1; s[2] += v2; s[3] += v3; s[4] += v4;
            s[5]  = fmaf(v4, v0, s[5]);
            s[6]  = fmaf(v4, v1, s[6]);
            s[7]  = fmaf(v4, v2, s[7]);
            s[8]  = fmaf(v4, v3, s[8]);
            s[9]  = fmaf(v0, v0, s[9]);
            s[10] = fmaf(v0, v1, s[10]);
            s[11] = fmaf(v0, v2, s[11]);
            s[12] = fmaf(v0, v3, s[12]);
            s[13] = fmaf(v1, v1, s[13]);
            s[14] = fmaf(v1, v2, s[14]);
            s[15] = fmaf(v1, v3, s[15]);
            s[16] = fmaf(v2, v2, s[16]);
            s[17] = fmaf(v2, v3, s[17]);
            s[18] = fmaf(v3, v3, s[18]);
        }
        float* hbase = hs + row * HP1 + x0;
#pragma unroll
        for (int c = 0; c < NCH; c++) hbase[c * HCH] = s[c];

#pragma unroll
        for (int j = 1; j < 4; j++) {
            int li = j + 16, ti = j - 1;
            float l0 = r0[li], l1 = r1[li], l2 = r2[li], l3 = r3[li], l4 = r4[li];
            float t0 = r0[ti], t1 = r1[ti], t2 = r2[ti], t3 = r3[ti], t4 = r4[ti];
            s[0] += l0 - t0; s[1] += l1 - t1; s[2] += l2 - t2;
            s[3] += l3 - t3; s[4] += l4 - t4;
            s[5]  = fmaf(-t4, t0, fmaf(l4, l0, s[5]));
            s[6]  = fmaf(-t4, t1, fmaf(l4, l1, s[6]));
            s[7]  = fmaf(-t4, t2, fmaf(l4, l2, s[7]));
            s[8]  = fmaf(-t4, t3, fmaf(l4, l3, s[8]));
            s[9]  = fmaf(-t0, t0, fmaf(l0, l0, s[9]));
            s[10] = fmaf(-t0, t1, fmaf(l0, l1, s[10]));
            s[11] = fmaf(-t0, t2, fmaf(l0, l2, s[11]));
            s[12] = fmaf(-t0, t3, fmaf(l0, l3, s[12]));
            s[13] = fmaf(-t1, t1, fmaf(l1, l1, s[13]));
            s[14] = fmaf(-t1, t2, fmaf(l1, l2, s[14]));
            s[15] = fmaf(-t1, t3, fmaf(l1, l3, s[15]));
            s[16] = fmaf(-t2, t2, fmaf(l2, l2, s[16]));
            s[17] = fmaf(-t2, t3, fmaf(l2, l3, s[17]));
            s[18] = fmaf(-t3, t3, fmaf(l3, l3, s[18]));
#pragma unroll
            for (int c = 0; c < NCH; c++) hbase[c * HCH + j] = s[c];
        }
    }
    __syncthreads();

    // ---- P2: vertical 17-tap box; task = (ch, col), slide 12 rows ----
    for (int t = tid; t < NCH * T1W; t += 512) {
        int c = t >> 5, col = t & 31;
        const float* h0 = hs + c * HCH + col;
        float s = 0.f;
#pragma unroll
        for (int j = 0; j < 17; j++) s += h0[j * HP1];
        float* o = out + (c * T1H) * T1W + col;
        o[0] = s;
#pragma unroll
        for (int y = 1; y < T1H; y++) {
            s += h0[(y + 16) * HP1] - h0[(y - 1) * HP1];
            o[y * T1W] = s;
        }
    }
    __syncthreads();

    // ---- P3: per-pixel 4x4 SPD solve  M x = 1  (384 px, 1/thread) ----
    if (tid < T1H * T1W) {
        int x = tid & 31, y = tid >> 5;
        float invN = frcp((float)(wcnt(X0 + x, Wn) * wcnt(Y0 + y, Hn)));

        float S[NCH];
#pragma unroll
        for (int c = 0; c < NCH; c++) S[c] = out[(c * T1H + y) * T1W + x];

        float m0 = S[0] * invN, m1 = S[1] * invN, m2 = S[2] * invN, m3 = S[3] * invN;
        float pm = S[4] * invN;
        float ip0 = S[5] * invN, ip1 = S[6] * invN, ip2 = S[7] * invN, ip3 = S[8] * invN;

        float Mm[4][4];
        Mm[0][0] = S[9]  * invN + EPSc;
        Mm[0][1] = Mm[1][0] = S[10] * invN;
        Mm[0][2] = Mm[2][0] = S[11] * invN;
        Mm[0][3] = Mm[3][0] = S[12] * invN;
        Mm[1][1] = S[13] * invN + EPSc;
        Mm[1][2] = Mm[2][1] = S[14] * invN;
        Mm[1][3] = Mm[3][1] = S[15] * invN;
        Mm[2][2] = S[16] * invN + EPSc;
        Mm[2][3] = Mm[3][2] = S[17] * invN;
        Mm[3][3] = S[18] * invN + EPSc;

        float xv[4] = {1.f, 1.f, 1.f, 1.f};
#pragma unroll
        for (int kk = 0; kk < 4; kk++) {
            float inv = frcp(Mm[kk][kk]);
#pragma unroll
            for (int j = 0; j < 4; j++) if (j > kk) Mm[kk][j] *= inv;
            xv[kk] *= inv;
#pragma unroll
            for (int i = 0; i < 4; i++) if (i > kk) {
                float f = Mm[i][kk];
#pragma unroll
                for (int j = 0; j < 4; j++) if (j > kk) Mm[i][j] -= f * Mm[kk][j];
                xv[i] -= f * xv[kk];
            }
        }
#pragma unroll
        for (int kk = 2; kk >= 0; kk--) {
#pragma unroll
            for (int j = 0; j < 4; j++) if (j > kk) xv[kk] -= Mm[kk][j] * xv[j];
        }

        float ft0 = ip0 - pm * m0;
        float ft1 = ip1 - pm * m1;
        float ft2 = ip2 - pm * m2;
        float ft3 = ip3 - pm * m3;
        float Asum = ft0 * xv[0] + ft1 * xv[1] + ft2 * xv[2] + ft3 * xv[3];
        float msum = m0 + m1 + m2 + m3;
        float bv   = pm - Asum * msum;

        size_t pix = ((size_t)b * Hn + (Y0 + y)) * Wn + (X0 + x);
        g_Ab[pix] = Asum;
        g_Ab[(size_t)Bn * Hn * Wn + pix] = bv;
    }
}

// ---------------------------------------------------------------------------
// Stage 2: fused 2D box of (Asum, b) + final combine. (unchanged, 51us)
// Tile 64x64, halo 8 -> extended 80x80. 512 threads.
// ---------------------------------------------------------------------------
#define T2 64
#define E2 80
#define RP2 81
#define HP2 65
#define SZ2_RAW (2 * E2 * RP2)
#define SZ2_HS  (2 * E2 * HP2)
#define SMEM2_BYTES ((SZ2_RAW + SZ2_HS) * 4)
#define YSEG 8

__global__ __launch_bounds__(512) void k_stage2(const float* __restrict__ I,
                                                float* __restrict__ q) {
    extern __shared__ float sm[];
    float* raw = sm;
    float* hsb = sm + SZ2_RAW;

    int b  = blockIdx.z;
    int X0 = blockIdx.x * T2, Y0 = blockIdx.y * T2;
    int tid = threadIdx.x;
    const size_t PL = (size_t)Bn * Hn * Wn;

    {
        bool intx = (X0 >= Rr) && (X0 + T2 + Rr <= Wn);
        for (int i = tid; i < 2 * E2 * 20; i += 512) {
            int pl  = i / (E2 * 20);
            int rem = i - pl * (E2 * 20);
            int ey  = rem / 20;
            int ex4 = rem - ey * 20;
            int gy  = Y0 - Rr + ey;
            int gx0 = X0 - Rr + ex4 * 4;
            const float* src = g_Ab + (size_t)pl * PL + (size_t)b * Hn * Wn;
            float4 v = make_float4(0.f, 0.f, 0.f, 0.f);
            if ((unsigned)gy < (unsigned)Hn) {
                if (intx) {
                    v = *reinterpret_cast<const float4*>(src + (size_t)gy * Wn + gx0);
                } else {
                    const float* r = src + (size_t)gy * Wn;
                    if ((unsigned)(gx0 + 0) < (unsigned)Wn) v.x = r[gx0 + 0];
                    if ((unsigned)(gx0 + 1) < (unsigned)Wn) v.y = r[gx0 + 1];
                    if ((unsigned)(gx0 + 2) < (unsigned)Wn) v.z = r[gx0 + 2];
                    if ((unsigned)(gx0 + 3) < (unsigned)Wn) v.w = r[gx0 + 3];
                }
            }
            float* d = raw + (pl * E2 + ey) * RP2 + ex4 * 4;
            d[0] = v.x; d[1] = v.y; d[2] = v.z; d[3] = v.w;
        }
    }
    __syncthreads();

    for (int t = tid; t < 2 * E2 * 4; t += 512) {
        int ch  = (t >= E2 * 4) ? 1 : 0;
        int rem = t - ch * E2 * 4;
        int ey  = rem >> 2;
        int x0  = (rem & 3) << 4;
        const float* ra = raw + (ch * E2 + ey) * RP2 + x0;
        float s = 0.f;
#pragma unroll
        for (int i = 0; i < 17; i++) s += ra[i];
        float* hrow = hsb + (ch * E2 + ey) * HP2 + x0;
        hrow[0] = s;
#pragma unroll
        for (int x = 1; x < 16; x++) {
            s += ra[x + 16] - ra[x - 1];
            hrow[x] = s;
        }
    }
    __syncthreads();

    {
        int col = tid & 63;
        int seg = tid >> 6;
        int ys  = seg * YSEG;
        const float* hA = hsb + col;
        const float* hB = hsb + (size_t)E2 * HP2 + col;

        float SA = 0.f, SB = 0.f;
#pragma unroll
        for (int j = 0; j < 17; j++) {
            SA += hA[(ys + j) * HP2];
            SB += hB[(ys + j) * HP2];
        }
        int gx = X0 + col;
        int cntx = wcnt(gx, Wn);
        const float* Ib = I + ((size_t)b * Cn) * Hn * Wn;

#pragma unroll
        for (int yy = 0; yy < YSEG; yy++) {
            int gy = Y0 + ys + yy;
            float invN = frcp((float)(wcnt(gy, Hn) * cntx));
            size_t row = (size_t)gy * Wn + gx;
            float isum = Ib[row]
                       + Ib[(size_t)Hn * Wn + row]
                       + Ib[(size_t)2 * Hn * Wn + row]
                       + Ib[(size_t)3 * Hn * Wn + row];
            q[((size_t)b * Hn + gy) * Wn + gx] = (SA * invN) * isum + SB * invN;

            if (yy < YSEG - 1) {
                int lead = ys + yy + 17, trail = ys + yy;
                SA += hA[lead * HP2] - hA[trail * HP2];
                SB += hB[lead * HP2] - hB[trail * HP2];
            }
        }
    }
}

extern "C" void kernel_launch(void* const* d_in, const int* in_sizes, int n_in,
                              void* d_out, int out_size) {
    const float* I = (const float*)d_in[0];
    const float* p = (const float*)d_in[1];
    float* q = (float*)d_out;

    static bool attr_done = false;
    if (!attr_done) {
        cudaFuncSetAttribute(k_stage1, cudaFuncAttributeMaxDynamicSharedMemorySize, SMEM1_BYTES);
        cudaFuncSetAttribute(k_stage2, cudaFuncAttributeMaxDynamicSharedMemorySize, SMEM2_BYTES);
        attr_done = true;
    }

    k_stage1<<<dim3(Wn / T1W, Hn / T1H, Bn), 512, SMEM1_BYTES>>>(I, p);
    k_stage2<<<dim3(Wn / T2, Hn / T2, Bn), 512, SMEM2_BYTES>>>(I, q);
}

// round 13
// speedup vs baseline: 2.5923x; 1.1833x over previous
#include <cuda_runtime.h>
#include <cstddef>

#define Bn 8
#define Cn 4
#define Hn 768
#define Wn 768
#define Rr 8
#define NCH 19
#define EPSc 1e-4f

// A-sum and b intermediate (only 2 channels survive stage 1)
__device__ float g_Ab[(size_t)2 * Bn * Hn * Wn];

__device__ __forceinline__ int wcnt(int t, int L) {
    int lo = t - Rr; if (lo < 0) lo = 0;
    int hi = t + Rr; if (hi > L - 1) hi = L - 1;
    return hi - lo + 1;
}

__device__ __forceinline__ float frcp(float x) {
    float r;
    asm("rcp.approx.f32 %0, %1;" : "=f"(r) : "f"(x));
    return r;
}

// ---------------------------------------------------------------------------
// Stage 1: vertical ring-buffer strip kernel.
// Block = 32-wide x 96-tall output strip, 8 steps of 12 rows.
// hs ring = 28 ext-rows (phys = lr mod 28). Output go needs ext rows
// [go, go+16]; after P1(s) (ext rows 12s+16..12s+27) the ring holds exactly
// [12s, 12s+27] = step s's full window. P2 running sums persist in registers.
// SMEM (floats):
//   hs   [0, 17556)      : 19 ch x 28 ring rows x 33
//   outb [17556, 24852)  : 19 x 12 x 32 = 7296  (also step-0 raw: 5x28x49=6860)
//   rawb [24852, 27792)  : 5 x 12 x 49 = 2940   (steady-state raw)
// total 27792 floats = 111168 B -> 2 CTAs/SM.
// ---------------------------------------------------------------------------
#define T1W 32
#define HSTEP 12
#define NSTEP 8
#define RING 28
#define RPW 49
#define HP1 33
#define HCH (RING * HP1)            // 924
#define SZ1_HS  (NCH * HCH)         // 17556
#define SZ1_OUT (NCH * HSTEP * T1W) // 7296
#define SZ1_RAW (5 * HSTEP * RPW)   // 2940
#define SMEM1_BYTES ((SZ1_HS + SZ1_OUT + SZ1_RAW) * 4)  // 111168

__device__ __forceinline__ float4 load_halo4(const float* __restrict__ src,
                                             int gy, int gx0, bool intx) {
    float4 v = make_float4(0.f, 0.f, 0.f, 0.f);
    if ((unsigned)gy < (unsigned)Hn) {
        if (intx) {
            v = *reinterpret_cast<const float4*>(src + (size_t)gy * Wn + gx0);
        } else {
            const float* r = src + (size_t)gy * Wn;
            if ((unsigned)(gx0 + 0) < (unsigned)Wn) v.x = r[gx0 + 0];
            if ((unsigned)(gx0 + 1) < (unsigned)Wn) v.y = r[gx0 + 1];
            if ((unsigned)(gx0 + 2) < (unsigned)Wn) v.z = r[gx0 + 2];
            if ((unsigned)(gx0 + 3) < (unsigned)Wn) v.w = r[gx0 + 3];
        }
    }
    return v;
}

// Horizontal 17-tap box of all 19 channels for one (row, 4-px seg) task.
__device__ __forceinline__ void p1_task(const float* __restrict__ rawp, int PS,
                                        int rowlocal, int phys, int seg,
                                        float* __restrict__ hs) {
    const float* r0 = rawp + rowlocal * RPW + seg * 4;
    const float* r1 = r0 + PS;
    const float* r2 = r1 + PS;
    const float* r3 = r2 + PS;
    const float* r4 = r3 + PS;

    float s[NCH];
#pragma unroll
    for (int c = 0; c < NCH; c++) s[c] = 0.f;

#pragma unroll
    for (int i = 0; i < 17; i++) {
        float v0 = r0[i], v1 = r1[i], v2 = r2[i], v3 = r3[i], v4 = r4[i];
        s[0] += v0; s[1] += v1; s[2] += v2; s[3] += v3; s[4] += v4;
        s[5]  = fmaf(v4, v0, s[5]);
        s[6]  = fmaf(v4, v1, s[6]);
        s[7]  = fmaf(v4, v2, s[7]);
        s[8]  = fmaf(v4, v3, s[8]);
        s[9]  = fmaf(v0, v0, s[9]);
        s[10] = fmaf(v0, v1, s[10]);
        s[11] = fmaf(v0, v2, s[11]);
        s[12] = fmaf(v0, v3, s[12]);
        s[13] = fmaf(v1, v1, s[13]);
        s[14] = fmaf(v1, v2, s[14]);
        s[15] = fmaf(v1, v3, s[15]);
        s[16] = fmaf(v2, v2, s[16]);
        s[17] = fmaf(v2, v3, s[17]);
        s[18] = fmaf(v3, v3, s[18]);
    }
    float* hbase = hs + phys * HP1 + seg * 4;
#pragma unroll
    for (int c = 0; c < NCH; c++) hbase[c * HCH] = s[c];

#pragma unroll
    for (int j = 1; j < 4; j++) {
        int li = j + 16, ti = j - 1;
        float l0 = r0[li], l1 = r1[li], l2 = r2[li], l3 = r3[li], l4 = r4[li];
        float t0 = r0[ti], t1 = r1[ti], t2 = r2[ti], t3 = r3[ti], t4 = r4[ti];
        s[0] += l0 - t0; s[1] += l1 - t1; s[2] += l2 - t2;
        s[3] += l3 - t3; s[4] += l4 - t4;
        s[5]  = fmaf(-t4, t0, fmaf(l4, l0, s[5]));
        s[6]  = fmaf(-t4, t1, fmaf(l4, l1, s[6]));
        s[7]  = fmaf(-t4, t2, fmaf(l4, l2, s[7]));
        s[8]  = fmaf(-t4, t3, fmaf(l4, l3, s[8]));
        s[9]  = fmaf(-t0, t0, fmaf(l0, l0, s[9]));
        s[10] = fmaf(-t0, t1, fmaf(l0, l1, s[10]));
        s[11] = fmaf(-t0, t2, fmaf(l0, l2, s[11]));
        s[12] = fmaf(-t0, t3, fmaf(l0, l3, s[12]));
        s[13] = fmaf(-t1, t1, fmaf(l1, l1, s[13]));
        s[14] = fmaf(-t1, t2, fmaf(l1, l2, s[14]));
        s[15] = fmaf(-t1, t3, fmaf(l1, l3, s[15]));
        s[16] = fmaf(-t2, t2, fmaf(l2, l2, s[16]));
        s[17] = fmaf(-t2, t3, fmaf(l2, l3, s[17]));
        s[18] = fmaf(-t3, t3, fmaf(l3, l3, s[18]));
#pragma unroll
        for (int c = 0; c < NCH; c++) hbase[c * HCH + j] = s[c];
    }
}

__global__ __launch_bounds__(512, 2) void k_stage1(const float* __restrict__ I,
                                                   const float* __restrict__ p) {
    extern __shared__ float sm[];
    float* hs   = sm;
    float* outb = sm + SZ1_HS;
    float* rawb = sm + SZ1_HS + SZ1_OUT;

    int b  = blockIdx.z;
    int X0 = blockIdx.x * T1W;
    int Y0 = blockIdx.y * (HSTEP * NSTEP);     // 96-row group
    int tid = threadIdx.x;
    const size_t HW = (size_t)Hn * Wn;
    const size_t PL = (size_t)Bn * Hn * Wn;
    bool intx = (X0 >= Rr) && (X0 + T1W + Rr <= Wn);

    // persistent P2 state (vertical running sums; all tasks share row sequence)
    float S0 = 0.f, S1 = 0.f;
    int leadp = 0, trailp = 0;
    int ch0 = tid >> 5, col0 = tid & 31;
    int ch1 = 16 + (tid >> 5);          // task tid+512 (valid when tid < 96)
    bool dual = (tid < 96);

    for (int s = 0; s < NSTEP; s++) {
        if (s == 0) {
            // ---- P0big: load ext rows lr 0..27 into outb (raw28) ----
            for (int i = tid; i < 5 * RING * 12; i += 512) {
                int pl  = i / (RING * 12);
                int rem = i - pl * (RING * 12);
                int lr  = rem / 12;
                int ex4 = rem - lr * 12;
                const float* src = (pl < 4) ? I + ((size_t)b * Cn + pl) * HW
                                            : p + (size_t)b * HW;
                float4 v = load_halo4(src, Y0 - 8 + lr, X0 - 8 + ex4 * 4, intx);
                float* d = outb + (pl * RING + lr) * RPW + ex4 * 4;
                d[0] = v.x; d[1] = v.y; d[2] = v.z; d[3] = v.w;
            }
            __syncthreads();
            // ---- P1big: 224 tasks, rows lr 0..27 (phys = lr) ----
            if (tid < 224)
                p1_task(outb, RING * RPW, tid >> 3, tid >> 3, tid & 7, hs);
            __syncthreads();
        } else {
            // ---- P1 steady: 96 tasks, rows lr = 12s+16 .. 12s+27 ----
            if (tid < 96) {
                int rl = tid >> 3;
                int lr = 12 * s + 16 + rl;
                p1_task(rawb, HSTEP * RPW, rl, lr % RING, tid & 7, hs);
            }
            __syncthreads();
        }

        // ---- Phase C: prefetch next raw (regs) + P2 vertical slide ----
        float4 pv0, pv1;
        int st0 = -1, st1 = -1;
        if (s < NSTEP - 1) {
            int ns = s + 1;
            {
                int i = tid;                 // task 0..511
                int pl  = i / 144;
                int rem = i - pl * 144;
                int lrl = rem / 12;
                int ex4 = rem - lrl * 12;
                int lr  = 12 * ns + 16 + lrl;
                const float* src = (pl < 4) ? I + ((size_t)b * Cn + pl) * HW
                                            : p + (size_t)b * HW;
                pv0 = load_halo4(src, Y0 - 8 + lr, X0 - 8 + ex4 * 4, intx);
                st0 = (pl * HSTEP + lrl) * RPW + ex4 * 4;
            }
            int i1 = tid + 512;
            if (i1 < 720) {                  // tasks 512..719
                int pl  = i1 / 144;
                int rem = i1 - pl * 144;
                int lrl = rem / 12;
                int ex4 = rem - lrl * 12;
                int lr  = 12 * ns + 16 + lrl;
                const float* src = (pl < 4) ? I + ((size_t)b * Cn + pl) * HW
                                            : p + (size_t)b * HW;
                pv1 = load_halo4(src, Y0 - 8 + lr, X0 - 8 + ex4 * 4, intx);
                st1 = (pl * HSTEP + lrl) * RPW + ex4 * 4;
            }
        }

        // P2: add lead rows; emit outputs; subtract trail rows.
        {
            int nIt = (s == 0) ? (16 + HSTEP) : HSTEP;   // 16 silent adds at s=0
            int yoff = (s == 0) ? -16 : 0;
            for (int k = 0; k < nIt; k++) {
                S0 += hs[ch0 * HCH + leadp * HP1 + col0];
                if (dual) S1 += hs[ch1 * HCH + leadp * HP1 + col0];
                leadp++; if (leadp == RING) leadp = 0;
                int y = k + yoff;
                if (y >= 0) {
                    outb[(ch0 * HSTEP + y) * T1W + col0] = S0;
                    if (dual) outb[(ch1 * HSTEP + y) * T1W + col0] = S1;
                    S0 -= hs[ch0 * HCH + trailp * HP1 + col0];
                    if (dual) S1 -= hs[ch1 * HCH + trailp * HP1 + col0];
                    trailp++; if (trailp == RING) trailp = 0;
                }
            }
        }

        // store prefetched raw rows
        if (st0 >= 0) {
            float* d = rawb + st0;
            d[0] = pv0.x; d[1] = pv0.y; d[2] = pv0.z; d[3] = pv0.w;
        }
        if (st1 >= 0) {
            float* d = rawb + st1;
            d[0] = pv1.x; d[1] = pv1.y; d[2] = pv1.z; d[3] = pv1.w;
        }
        __syncthreads();

        // ---- P3: per-pixel 4x4 SPD solve  M x = 1  (384 px) ----
        if (tid < HSTEP * T1W) {
            int x = tid & 31, y = tid >> 5;
            int gy = Y0 + 12 * s + y;
            int gx = X0 + x;
            float invN = frcp((float)(wcnt(gx, Wn) * wcnt(gy, Hn)));

            float S[NCH];
#pragma unroll
            for (int c = 0; c < NCH; c++) S[c] = outb[(c * HSTEP + y) * T1W + x];

            float m0 = S[0] * invN, m1 = S[1] * invN, m2 = S[2] * invN, m3 = S[3] * invN;
            float pm = S[4] * invN;
            float ip0 = S[5] * invN, ip1 = S[6] * invN, ip2 = S[7] * invN, ip3 = S[8] * invN;

            float Mm[4][4];
            Mm[0][0] = S[9]  * invN + EPSc;
            Mm[0][1] = Mm[1][0] = S[10] * invN;
            Mm[0][2] = Mm[2][0] = S[11] * invN;
            Mm[0][3] = Mm[3][0] = S[12] * invN;
            Mm[1][1] = S[13] * invN + EPSc;
            Mm[1][2] = Mm[2][1] = S[14] * invN;
            Mm[1][3] = Mm[3][1] = S[15] * invN;
            Mm[2][2] = S[16] * invN + EPSc;
            Mm[2][3] = Mm[3][2] = S[17] * invN;
            Mm[3][3] = S[18] * invN + EPSc;

            float xv[4] = {1.f, 1.f, 1.f, 1.f};
#pragma unroll
            for (int kk = 0; kk < 4; kk++) {
                float inv = frcp(Mm[kk][kk]);
#pragma unroll
                for (int j = 0; j < 4; j++) if (j > kk) Mm[kk][j] *= inv;
                xv[kk] *= inv;
#pragma unroll
                for (int i = 0; i < 4; i++) if (i > kk) {
                    float f = Mm[i][kk];
#pragma unroll
                    for (int j = 0; j < 4; j++) if (j > kk) Mm[i][j] -= f * Mm[kk][j];
                    xv[i] -= f * xv[kk];
                }
            }
#pragma unroll
            for (int kk = 2; kk >= 0; kk--) {
#pragma unroll
                for (int j = 0; j < 4; j++) if (j > kk) xv[kk] -= Mm[kk][j] * xv[j];
            }

            float ft0 = ip0 - pm * m0;
            float ft1 = ip1 - pm * m1;
            float ft2 = ip2 - pm * m2;
            float ft3 = ip3 - pm * m3;
            float Asum = ft0 * xv[0] + ft1 * xv[1] + ft2 * xv[2] + ft3 * xv[3];
            float msum = m0 + m1 + m2 + m3;
            float bv   = pm - Asum * msum;

            size_t pix = ((size_t)b * Hn + gy) * Wn + gx;
            g_Ab[pix] = Asum;
            g_Ab[PL + pix] = bv;
        }
        __syncthreads();
    }
}

// ---------------------------------------------------------------------------
// Stage 2: fused 2D box of (Asum, b) + final combine. (unchanged, 50us)
// ---------------------------------------------------------------------------
#define T2 64
#define E2 80
#define RP2 81
#define HP2 65
#define SZ2_RAW (2 * E2 * RP2)
#define SZ2_HS  (2 * E2 * HP2)
#define SMEM2_BYTES ((SZ2_RAW + SZ2_HS) * 4)
#define YSEG 8

__global__ __launch_bounds__(512) void k_stage2(const float* __restrict__ I,
                                                float* __restrict__ q) {
    extern __shared__ float sm[];
    float* raw = sm;
    float* hsb = sm + SZ2_RAW;

    int b  = blockIdx.z;
    int X0 = blockIdx.x * T2, Y0 = blockIdx.y * T2;
    int tid = threadIdx.x;
    const size_t PL = (size_t)Bn * Hn * Wn;

    {
        bool intx = (X0 >= Rr) && (X0 + T2 + Rr <= Wn);
        for (int i = tid; i < 2 * E2 * 20; i += 512) {
            int pl  = i / (E2 * 20);
            int rem = i - pl * (E2 * 20);
            int ey  = rem / 20;
            int ex4 = rem - ey * 20;
            int gy  = Y0 - Rr + ey;
            int gx0 = X0 - Rr + ex4 * 4;
            const float* src = g_Ab + (size_t)pl * PL + (size_t)b * Hn * Wn;
            float4 v = make_float4(0.f, 0.f, 0.f, 0.f);
            if ((unsigned)gy < (unsigned)Hn) {
                if (intx) {
                    v = *reinterpret_cast<const float4*>(src + (size_t)gy * Wn + gx0);
                } else {
                    const float* r = src + (size_t)gy * Wn;
                    if ((unsigned)(gx0 + 0) < (unsigned)Wn) v.x = r[gx0 + 0];
                    if ((unsigned)(gx0 + 1) < (unsigned)Wn) v.y = r[gx0 + 1];
                    if ((unsigned)(gx0 + 2) < (unsigned)Wn) v.z = r[gx0 + 2];
                    if ((unsigned)(gx0 + 3) < (unsigned)Wn) v.w = r[gx0 + 3];
                }
            }
            float* d = raw + (pl * E2 + ey) * RP2 + ex4 * 4;
            d[0] = v.x; d[1] = v.y; d[2] = v.z; d[3] = v.w;
        }
    }
    __syncthreads();

    for (int t = tid; t < 2 * E2 * 4; t += 512) {
        int ch  = (t >= E2 * 4) ? 1 : 0;
        int rem = t - ch * E2 * 4;
        int ey  = rem >> 2;
        int x0  = (rem & 3) << 4;
        const float* ra = raw + (ch * E2 + ey) * RP2 + x0;
        float s = 0.f;
#pragma unroll
        for (int i = 0; i < 17; i++) s += ra[i];
        float* hrow = hsb + (ch * E2 + ey) * HP2 + x0;
        hrow[0] = s;
#pragma unroll
        for (int x = 1; x < 16; x++) {
            s += ra[x + 16] - ra[x - 1];
            hrow[x] = s;
        }
    }
    __syncthreads();

    {
        int col = tid & 63;
        int seg = tid >> 6;
        int ys  = seg * YSEG;
        const float* hA = hsb + col;
        const float* hB = hsb + (size_t)E2 * HP2 + col;

        float SA = 0.f, SB = 0.f;
#pragma unroll
        for (int j = 0; j < 17; j++) {
            SA += hA[(ys + j) * HP2];
            SB += hB[(ys + j) * HP2];
        }
        int gx = X0 + col;
        int cntx = wcnt(gx, Wn);
        const float* Ib = I + ((size_t)b * Cn) * Hn * Wn;

#pragma unroll
        for (int yy = 0; yy < YSEG; yy++) {
            int gy = Y0 + ys + yy;
            float invN = frcp((float)(wcnt(gy, Hn) * cntx));
            size_t row = (size_t)gy * Wn + gx;
            float isum = Ib[row]
                       + Ib[(size_t)Hn * Wn + row]
                       + Ib[(size_t)2 * Hn * Wn + row]
                       + Ib[(size_t)3 * Hn * Wn + row];
            q[((size_t)b * Hn + gy) * Wn + gx] = (SA * invN) * isum + SB * invN;

            if (yy < YSEG - 1) {
                int lead = ys + yy + 17, trail = ys + yy;
                SA += hA[lead * HP2] - hA[trail * HP2];
                SB += hB[lead * HP2] - hB[trail * HP2];
            }
        }
    }
}

extern "C" void kernel_launch(void* const* d_in, const int* in_sizes, int n_in,
                              void* d_out, int out_size) {
    const float* I = (const float*)d_in[0];
    const float* p = (const float*)d_in[1];
    float* q = (float*)d_out;

    static bool attr_done = false;
    if (!attr_done) {
        cudaFuncSetAttribute(k_stage1, cudaFuncAttributeMaxDynamicSharedMemorySize, SMEM1_BYTES);
        cudaFuncSetAttribute(k_stage2, cudaFuncAttributeMaxDynamicSharedMemorySize, SMEM2_BYTES);
        attr_done = true;
    }

    k_stage1<<<dim3(Wn / T1W, Hn / (HSTEP * NSTEP), Bn), 512, SMEM1_BYTES>>>(I, p);
    k_stage2<<<dim3(Wn / T2, Hn / T2, Bn), 512, SMEM2_BYTES>>>(I, q);
}